// round 8
// baseline (speedup 1.0000x reference)
#include <cuda_runtime.h>
#include <cstdint>

// Dynamic 5x5 per-pixel convolution + leaky_relu(0.2), replicate padding.
// x:      (N, C, H, W)    f32  -> 8 MB   (staged per CTA via cp.async)
// kernel: (N, C*25, H, W) f32  -> 200 MB (dominant HBM stream, read once)
// out:    (N, C, H, W)    f32  -> 8 MB
//
// R7: seamless tap stream. The (rr, k1) loops are flattened into one fully
// unrolled 20-row loop with lookahead-1 double buffering, so 5 LDG.128 are
// ALWAYS in flight until the very last row (no per-rr prefetch seams).
// All tap/store offsets are compile-time immediates off one base pointer.

#define W_DIM 256
#define H_DIM 256
#define HW (W_DIM * H_DIM)
#define KS 5
#define PAD 2
#define ROWS_PER_CTA 8
#define ROWS_PER_THREAD 4
#define NROWS (ROWS_PER_THREAD * KS)         // 20 flattened row-loads
#define TILE_ROWS (ROWS_PER_CTA + 2 * PAD)   // 12
#define SROW 264                             // 256 + 2*PAD, padded
#define NTHREADS 128

__device__ __forceinline__ void cp_async4(uint32_t smem_addr, const float* gptr) {
    asm volatile("cp.async.ca.shared.global [%0], [%1], 4;"
                 :: "r"(smem_addr), "l"(gptr));
}

__global__ __launch_bounds__(NTHREADS, 8)
void dynconv5x5_kernel(const float* __restrict__ x,
                       const float* __restrict__ kern,
                       float* __restrict__ out)
{
    __shared__ float xs[TILE_ROWS][SROW];

    const int nc    = blockIdx.x >> 5;                   // plane index (0..31)
    const int hbase = (blockIdx.x & 31) * ROWS_PER_CTA;  // strip start row
    const int tx    = threadIdx.x;                       // 0..63 -> 4-px group
    const int ty    = threadIdx.y;                       // 0..1
    const int tid   = ty * 64 + tx;
    const int wbase = tx * 4;

    const float* xp = x + (size_t)nc * HW;

    // Single bases; every tap/store address below is base + constexpr offset.
    const float* kbase = kern + (size_t)nc * 25 * HW
                              + (size_t)(hbase + ty) * W_DIM + wbase;
    float* obase = out + (size_t)nc * HW + (size_t)(hbase + ty) * W_DIM + wbase;

    // ---- stage strip + halo via cp.async (replicate clamp at fill) ----
    uint32_t xs_base;
    asm("{ .reg .u64 t; cvta.to.shared.u64 t, %1; cvt.u32.u64 %0, t; }"
        : "=r"(xs_base) : "l"(&xs[0][0]));

    for (int idx = tid; idx < TILE_ROWS * SROW; idx += NTHREADS) {
        int r = idx / SROW;
        int c = idx - r * SROW;
        int gy = hbase + r - PAD;
        gy = gy < 0 ? 0 : (gy > H_DIM - 1 ? H_DIM - 1 : gy);
        int gx = c - PAD;
        gx = gx < 0 ? 0 : (gx > W_DIM - 1 ? W_DIM - 1 : gx);
        cp_async4(xs_base + (uint32_t)idx * 4u, xp + gy * W_DIM + gx);
    }
    asm volatile("cp.async.commit_group;");

    // ---- prefetch flattened row 0 (rr=0, k1=0) BEFORE the stage wait ----
    float4 kv[2][KS];
    #pragma unroll
    for (int k2 = 0; k2 < KS; k2++)
        kv[0][k2] = __ldcs((const float4*)(kbase + (size_t)k2 * HW));

    asm volatile("cp.async.wait_group 0;");
    __syncthreads();   // the ONLY barrier

    float acc0 = 0.f, acc1 = 0.f, acc2 = 0.f, acc3 = 0.f;

    // Flattened row stream: i -> (rr = i/5, k1 = i%5). Row i+1's 5 taps are
    // issued while row i is consumed; the stream never drains until i=19.
    #pragma unroll
    for (int i = 0; i < NROWS; i++) {
        const int rr  = i / KS;
        const int k1  = i - rr * KS;
        const int cur = i & 1;

        if (i < NROWS - 1) {
            const int rn  = (i + 1) / KS;
            const int k1n = (i + 1) - rn * KS;
            #pragma unroll
            for (int k2 = 0; k2 < KS; k2++)
                kv[cur ^ 1][k2] = __ldcs((const float4*)(
                    kbase + (size_t)((2 * rn) * W_DIM) + (size_t)((k1n * KS + k2)) * HW));
        }

        // 8-float sliding window from smem (aligned LDS.128 x2);
        // output-local row = ty + 2*rr, xs row = that + k1.
        const int xrow = ty + 2 * rr + k1;
        float4 a = *(const float4*)&xs[xrow][wbase];
        float4 b = *(const float4*)&xs[xrow][wbase + 4];
        float r[8] = {a.x, a.y, a.z, a.w, b.x, b.y, b.z, b.w};

        #pragma unroll
        for (int k2 = 0; k2 < KS; k2++) {
            float4 c4 = kv[cur][k2];
            acc0 = fmaf(c4.x, r[k2 + 0], acc0);
            acc1 = fmaf(c4.y, r[k2 + 1], acc1);
            acc2 = fmaf(c4.z, r[k2 + 2], acc2);
            acc3 = fmaf(c4.w, r[k2 + 3], acc3);
        }

        if (k1 == KS - 1) {
            // finished output row (hbase + ty + 2*rr): leaky_relu + store
            float o0 = acc0 >= 0.f ? acc0 : 0.2f * acc0;
            float o1 = acc1 >= 0.f ? acc1 : 0.2f * acc1;
            float o2 = acc2 >= 0.f ? acc2 : 0.2f * acc2;
            float o3 = acc3 >= 0.f ? acc3 : 0.2f * acc3;
            __stcs((float4*)(obase + (size_t)((2 * rr) * W_DIM)),
                   make_float4(o0, o1, o2, o3));
            acc0 = acc1 = acc2 = acc3 = 0.f;
        }
    }
}

extern "C" void kernel_launch(void* const* d_in, const int* in_sizes, int n_in,
                              void* d_out, int out_size)
{
    const float* x    = (const float*)d_in[0];
    const float* kern = (const float*)d_in[1];
    float* out        = (float*)d_out;

    const int NC = in_sizes[0] / HW;              // 32 for (4,8,256,256)

    dim3 block(64, 2);
    dim3 grid(NC * (H_DIM / ROWS_PER_CTA));       // 32 * 32 = 1024 CTAs
    dynconv5x5_kernel<<<grid, block>>>(x, kern, out);
}

// round 10
// speedup vs baseline: 1.1178x; 1.1178x over previous
#include <cuda_runtime.h>
#include <cstdint>

// Dynamic 5x5 per-pixel convolution + leaky_relu(0.2), replicate padding.
// x:      (N, C, H, W)    f32  -> 8 MB   (staged per CTA via cp.async.16B)
// kernel: (N, C*25, H, W) f32  -> 200 MB (dominant HBM stream, read once)
// out:    (N, C, H, W)    f32  -> 8 MB
//
// R8 = R5 (best: 512 CTAs x 256 thr, 16-row strips, one sync, row-0 tap
// prefetch under the stage wait, double-buffered tap rows, __stcs) with the
// x stage vectorized: interior staged as 16B cp.async (both sides aligned
// via a +4-column smem shift), edges as 4 scalar cp.async per row.
// Stage issue count drops 5280 -> 1360 ops/CTA.

#define W_DIM 256
#define H_DIM 256
#define HW (W_DIM * H_DIM)
#define KS 5
#define PAD 2
#define ROWS_PER_CTA 16
#define ROWS_PER_THREAD 4
#define TILE_ROWS (ROWS_PER_CTA + 2 * PAD)   // 20
#define SROW 272                             // 16B-aligned row stride
#define COL0 4                               // smem col = gx + COL0
#define NTHREADS 256

__device__ __forceinline__ void cp_async16(uint32_t smem_addr, const float* gptr) {
    asm volatile("cp.async.cg.shared.global [%0], [%1], 16;"
                 :: "r"(smem_addr), "l"(gptr));
}
__device__ __forceinline__ void cp_async4(uint32_t smem_addr, const float* gptr) {
    asm volatile("cp.async.ca.shared.global [%0], [%1], 4;"
                 :: "r"(smem_addr), "l"(gptr));
}

__global__ __launch_bounds__(NTHREADS, 4)
void dynconv5x5_kernel(const float* __restrict__ x,
                       const float* __restrict__ kern,
                       float* __restrict__ out)
{
    __shared__ float xs[TILE_ROWS][SROW];

    const int nc    = blockIdx.x >> 4;                   // plane index (0..31)
    const int hbase = (blockIdx.x & 15) * ROWS_PER_CTA;  // strip start row
    const int tx    = threadIdx.x;                       // 0..63 -> 4-px group
    const int ty    = threadIdx.y;                       // 0..3
    const int tid   = ty * 64 + tx;
    const int wbase = tx * 4;

    const float* xp    = x    + (size_t)nc * HW;
    const float* kpl   = kern + (size_t)nc * 25 * HW;
    float*       outpl = out  + (size_t)nc * HW;

    uint32_t xs_base;
    asm("{ .reg .u64 t; cvta.to.shared.u64 t, %1; cvt.u32.u64 %0, t; }"
        : "=r"(xs_base) : "l"(&xs[0][0]));

    // ---- stage interior: 20 rows x 64 aligned float4 groups (16B cp.async) ----
    for (int i = tid; i < TILE_ROWS * (W_DIM / 4); i += NTHREADS) {
        int r = i >> 6;                 // row 0..19
        int g = i & 63;                 // float4 group, gx = 4g
        int gy = hbase + r - PAD;
        gy = gy < 0 ? 0 : (gy > H_DIM - 1 ? H_DIM - 1 : gy);
        cp_async16(xs_base + (uint32_t)(r * SROW + COL0 + 4 * g) * 4u,
                   xp + gy * W_DIM + 4 * g);
    }
    // ---- stage edges: 4 clamped scalars per row (cols 2,3 -> x[,0]; 260,261 -> x[,255]) ----
    for (int i = tid; i < TILE_ROWS * 4; i += NTHREADS) {
        int r = i >> 2;
        int e = i & 3;
        int gy = hbase + r - PAD;
        gy = gy < 0 ? 0 : (gy > H_DIM - 1 ? H_DIM - 1 : gy);
        int col = (e < 2) ? (2 + e) : (258 + e);          // 2,3,260,261
        int gx  = (e < 2) ? 0 : (W_DIM - 1);
        cp_async4(xs_base + (uint32_t)(r * SROW + col) * 4u,
                  xp + gy * W_DIM + gx);
    }
    asm volatile("cp.async.commit_group;");

    // ---- prefetch row-0 taps (rr=0) BEFORE the stage wait ----
    float4 kv[2][KS];
    {
        const int h0 = hbase + ty;
        const float* kb0 = kpl + (size_t)h0 * W_DIM + wbase;
        #pragma unroll
        for (int k2 = 0; k2 < KS; k2++)
            kv[0][k2] = __ldcs((const float4*)(kb0 + (size_t)k2 * HW));
    }

    asm volatile("cp.async.wait_group 0;");
    __syncthreads();   // the ONLY barrier

    // Each thread: rows hbase + ty + 4*rr, rr = 0..3
    #pragma unroll 1
    for (int rr = 0; rr < ROWS_PER_THREAD; rr++) {
        const int hloc = ty + rr * 4;            // row within strip (0..15)
        const int h    = hbase + hloc;           // global row
        const float* kbase = kpl + (size_t)h * W_DIM + wbase;

        if (rr > 0) {   // rr=0's kv[0] was preloaded under the stage wait
            #pragma unroll
            for (int k2 = 0; k2 < KS; k2++)
                kv[0][k2] = __ldcs((const float4*)(kbase + (size_t)k2 * HW));
        }

        float acc0 = 0.f, acc1 = 0.f, acc2 = 0.f, acc3 = 0.f;

        #pragma unroll
        for (int k1 = 0; k1 < KS; k1++) {
            const int cur = k1 & 1;
            if (k1 < KS - 1) {
                #pragma unroll
                for (int k2 = 0; k2 < KS; k2++)
                    kv[cur ^ 1][k2] =
                        __ldcs((const float4*)(kbase + (size_t)((k1 + 1) * KS + k2) * HW));
            }

            // 12-float window (3 aligned LDS.128); cols wbase..wbase+11,
            // i.e. gx = wbase-4 .. wbase+7; taps use gx wbase-2+k2+i -> arr[k2+2+i]
            float4 a = *(const float4*)&xs[hloc + k1][wbase];
            float4 b = *(const float4*)&xs[hloc + k1][wbase + 4];
            float4 c = *(const float4*)&xs[hloc + k1][wbase + 8];
            float arr[12] = {a.x, a.y, a.z, a.w, b.x, b.y, b.z, b.w,
                             c.x, c.y, c.z, c.w};

            #pragma unroll
            for (int k2 = 0; k2 < KS; k2++) {
                float4 c4 = kv[cur][k2];
                acc0 = fmaf(c4.x, arr[k2 + 2], acc0);
                acc1 = fmaf(c4.y, arr[k2 + 3], acc1);
                acc2 = fmaf(c4.z, arr[k2 + 4], acc2);
                acc3 = fmaf(c4.w, arr[k2 + 5], acc3);
            }
        }

        // leaky_relu(0.2) + streaming store of this row's 4 px
        acc0 = acc0 >= 0.f ? acc0 : 0.2f * acc0;
        acc1 = acc1 >= 0.f ? acc1 : 0.2f * acc1;
        acc2 = acc2 >= 0.f ? acc2 : 0.2f * acc2;
        acc3 = acc3 >= 0.f ? acc3 : 0.2f * acc3;

        __stcs((float4*)(outpl + (size_t)h * W_DIM + wbase),
               make_float4(acc0, acc1, acc2, acc3));
    }
}

extern "C" void kernel_launch(void* const* d_in, const int* in_sizes, int n_in,
                              void* d_out, int out_size)
{
    const float* x    = (const float*)d_in[0];
    const float* kern = (const float*)d_in[1];
    float* out        = (float*)d_out;

    const int NC = in_sizes[0] / HW;              // 32 for (4,8,256,256)

    dim3 block(64, 4);
    dim3 grid(NC * (H_DIM / ROWS_PER_CTA));       // 512 CTAs, single wave
    dynconv5x5_kernel<<<grid, block>>>(x, kern, out);
}